// round 5
// baseline (speedup 1.0000x reference)
#include <cuda_runtime.h>
#include <cuda_bf16.h>

#define C_IN   64
#define C_OUT  128
#define BEV_H  512
#define BEV_W  512
#define BATCH  2
#define NKER   16

#define N_CELLS      (BATCH * BEV_H * BEV_W)        // 524288
#define BITMAP_WORDS (N_CELLS / 32)                 // 16384
#define MAX_PTS      (1 << 17)                      // 131072 (N=40000)
#define CAP          192                            // staged cells per row
#define STAGE_PITCH  129                            // bank-conflict pad
#define STAGE_BYTES  (CAP * STAGE_PITCH * 4)        // ~99 KB dynamic smem

// Invariant: g_scratch and g_bitmap are ALL-ZERO at every kernel_launch entry.
// (zero at module load; expand_kernel restores zeros for cells it consumed.)
__device__ float        g_scratch[(size_t)N_CELLS * C_OUT];   // [cell][C_OUT]
__device__ unsigned int g_bitmap[BITMAP_WORDS];
__device__ int          g_hist[NKER];
__device__ int          g_cursor[NKER];
__device__ int          g_order[MAX_PTS];

// ---------------------------------------------------------------- tiny helpers
__global__ void clear_hist_kernel()
{
    if (threadIdx.x < NKER) g_hist[threadIdx.x] = 0;
}

__global__ void hist_kernel(const int* __restrict__ coords,
                            const int* __restrict__ stride_p, int n)
{
    __shared__ int h[NKER];
    if (threadIdx.x < NKER) h[threadIdx.x] = 0;
    __syncthreads();
    int i = blockIdx.x * blockDim.x + threadIdx.x;
    if (i < n) {
        int kidx = coords[i * 4 + 1] / stride_p[0];
        atomicAdd(&h[kidx], 1);
    }
    __syncthreads();
    if (threadIdx.x < NKER) atomicAdd(&g_hist[threadIdx.x], h[threadIdx.x]);
}

__global__ void prefix_kernel()
{
    if (threadIdx.x == 0) {
        int acc = 0;
        for (int b = 0; b < NKER; b++) { g_cursor[b] = acc; acc += g_hist[b]; }
    }
}

__global__ void reorder_kernel(const int* __restrict__ coords,
                               const int* __restrict__ stride_p, int n)
{
    __shared__ int h[NKER];
    __shared__ int base[NKER];
    if (threadIdx.x < NKER) h[threadIdx.x] = 0;
    __syncthreads();
    int i = blockIdx.x * blockDim.x + threadIdx.x;
    int bin = 0, rank = 0;
    if (i < n) {
        bin = coords[i * 4 + 1] / stride_p[0];
        rank = atomicAdd(&h[bin], 1);
    }
    __syncthreads();
    if (threadIdx.x < NKER)
        base[threadIdx.x] = atomicAdd(&g_cursor[threadIdx.x], h[threadIdx.x]);
    __syncthreads();
    if (i < n) g_order[base[bin] + rank] = i;
}

// --------------------------------------------------- matvec + coalesced scatter
// One warp per point, points visited in kidx-sorted order so each block's 8
// warps share one 32KB weight matrix (L1-resident). Lane l owns channels
// [4l,4l+3]; contributions land in a CONTIGUOUS 512B scratch cell.
__global__ void scatter_kernel(const int* __restrict__ coords,
                               const float* __restrict__ feats,
                               const float* __restrict__ kernel,
                               const int* __restrict__ stride_p,
                               int n_points)
{
    int wid  = (blockIdx.x * blockDim.x + threadIdx.x) >> 5;
    int lane = threadIdx.x & 31;
    if (wid >= n_points) return;

    int p = g_order[wid];

    int s  = stride_p[0];
    int4 c4 = ((const int4*)coords)[p];
    int cell = c4.w * (BEV_H * BEV_W) + (c4.x / s) * BEV_W + (c4.z / s);
    int kidx = c4.y / s;

    const float* fp = feats + (size_t)p * C_IN;
    float f0 = fp[lane];
    float f1 = fp[lane + 32];

    const float4* kp = (const float4*)(kernel + (size_t)kidx * C_IN * C_OUT);

    float4 acc = make_float4(0.f, 0.f, 0.f, 0.f);
#pragma unroll
    for (int k = 0; k < C_IN; k++) {
        float fk = __shfl_sync(0xFFFFFFFFu, (k < 32) ? f0 : f1, k & 31);
        float4 w = kp[k * (C_OUT / 4) + lane];
        acc.x = fmaf(fk, w.x, acc.x);
        acc.y = fmaf(fk, w.y, acc.y);
        acc.z = fmaf(fk, w.z, acc.z);
        acc.w = fmaf(fk, w.w, acc.w);
    }

    float* dst = g_scratch + (size_t)cell * C_OUT + lane * 4;
    atomicAdd(dst + 0, acc.x);
    atomicAdd(dst + 1, acc.y);
    atomicAdd(dst + 2, acc.z);
    atomicAdd(dst + 3, acc.w);

    if (lane == 0)
        atomicOr(&g_bitmap[cell >> 5], 1u << (cell & 31));
}

// ------------------------------------------------------- expand / transpose out
// One block per (b,x) row. Stage occupied cells into smem with coalesced 512B
// reads, stream the output with __stcs float4 stores, then RESTORE the
// all-zero invariant (zero consumed scratch cells + clear bitmap words).
__global__ void expand_kernel(float* __restrict__ out)
{
    extern __shared__ float staged[];              // [CAP][STAGE_PITCH]
    __shared__ short slot_of_z[BEV_W];
    __shared__ short z_of_slot[BEV_W];
    __shared__ unsigned int bits[BEV_W / 32];
    __shared__ int nslots;

    int row = blockIdx.x;                          // b * BEV_H + x
    int b   = row >> 9;
    int x   = row & (BEV_H - 1);
    int tid = threadIdx.x;

    if (tid < BEV_W / 32) bits[tid] = g_bitmap[row * (BEV_W / 32) + tid];
    if (tid == 0) nslots = 0;
    __syncthreads();

    // Phase A: compact occupied z's into slots.
#pragma unroll
    for (int z = tid; z < BEV_W; z += 256) {
        if ((bits[z >> 5] >> (z & 31)) & 1u) {
            int s = atomicAdd(&nslots, 1);
            slot_of_z[z] = (short)s;
            z_of_slot[s] = (short)z;
        } else {
            slot_of_z[z] = -1;
        }
    }
    __syncthreads();

    int ns = nslots;
    int nstage = ns < CAP ? ns : CAP;
    float* srow = g_scratch + (size_t)row * BEV_W * C_OUT;

    // Phase B: coalesced 512B-per-cell loads into padded smem.
    for (int i = tid; i < nstage * C_OUT; i += 256) {
        int s = i >> 7, c = i & 127;
        staged[s * STAGE_PITCH + c] = srow[(size_t)z_of_slot[s] * C_OUT + c];
    }
    __syncthreads();

    // Phase C: stream output. thread -> (z-float4 q, channel parity).
    int q  = tid & 127;
    int cp = tid >> 7;
    int z0 = q * 4;
    int s0 = slot_of_z[z0 + 0];
    int s1 = slot_of_z[z0 + 1];
    int s2 = slot_of_z[z0 + 2];
    int s3 = slot_of_z[z0 + 3];

#pragma unroll 4
    for (int cb = 0; cb < C_OUT; cb += 2) {
        int c = cb + cp;
        float4 v;
        v.x = (s0 < 0) ? 0.f : (s0 < CAP ? staged[s0 * STAGE_PITCH + c]
                                         : srow[(size_t)(z0 + 0) * C_OUT + c]);
        v.y = (s1 < 0) ? 0.f : (s1 < CAP ? staged[s1 * STAGE_PITCH + c]
                                         : srow[(size_t)(z0 + 1) * C_OUT + c]);
        v.z = (s2 < 0) ? 0.f : (s2 < CAP ? staged[s2 * STAGE_PITCH + c]
                                         : srow[(size_t)(z0 + 2) * C_OUT + c]);
        v.w = (s3 < 0) ? 0.f : (s3 < CAP ? staged[s3 * STAGE_PITCH + c]
                                         : srow[(size_t)(z0 + 3) * C_OUT + c]);
        size_t o = (((size_t)(b * C_OUT + c) * BEV_H + x) * BEV_W) >> 2;
        __stcs(((float4*)out) + o + q, v);
    }
    __syncthreads();

    // Phase D: restore invariant — zero consumed cells, clear bitmap.
    for (int i = tid; i < ns * C_OUT; i += 256) {
        int s = i >> 7, c = i & 127;
        srow[(size_t)z_of_slot[s] * C_OUT + c] = 0.f;
    }
    if (tid < BEV_W / 32) g_bitmap[row * (BEV_W / 32) + tid] = 0u;
}

extern "C" void kernel_launch(void* const* d_in, const int* in_sizes, int n_in,
                              void* d_out, int out_size)
{
    const int*   coords = (const int*)d_in[0];
    const float* feats  = (const float*)d_in[1];
    const float* kern   = (const float*)d_in[2];
    const int*   stride = (const int*)d_in[3];

    int n_points = in_sizes[1] / C_IN;

    cudaFuncSetAttribute(expand_kernel,
                         cudaFuncAttributeMaxDynamicSharedMemorySize,
                         STAGE_BYTES);

    int tblocks = (n_points + 255) / 256;

    // 1-3. counting sort of point indices by kidx (16 bins)
    clear_hist_kernel<<<1, 32>>>();
    hist_kernel<<<tblocks, 256>>>(coords, stride, n_points);
    prefix_kernel<<<1, 32>>>();
    reorder_kernel<<<tblocks, 256>>>(coords, stride, n_points);

    // 4. matvec + coalesced atomic scatter (kidx-grouped for L1 reuse)
    int wpb = 8;
    int blocks = (n_points + wpb - 1) / wpb;
    scatter_kernel<<<blocks, wpb * 32>>>(coords, feats, kern, stride, n_points);

    // 5. stream final output + restore zero-scratch invariant
    expand_kernel<<<BATCH * BEV_H, 256, STAGE_BYTES>>>((float*)d_out);
}

// round 7
// speedup vs baseline: 1.1674x; 1.1674x over previous
#include <cuda_runtime.h>
#include <cuda_bf16.h>

#define C_IN   64
#define C_OUT  128
#define BEV_H  512
#define BEV_W  512
#define BATCH  2

#define N_CELLS  (BATCH * BEV_H * BEV_W)     // 524288
#define MAX_PTS  (1 << 17)                   // 131072 (N=40000)
#define CAP      80                          // staged cells per row
#define PITCH    129                         // odd pitch -> conflict-free

// Invariant: g_head is ALL-ZERO at every kernel_launch entry (zero at module
// load; expand_kernel resets every entry it consumed). 0 = empty, else p+1.
__device__ int   g_head[N_CELLS];                       // 2 MB
__device__ int   g_next[MAX_PTS];                       // chain links
__device__ float g_pointbuf[(size_t)MAX_PTS * C_OUT];   // 67 MB, ~20MB touched

// ------------------------------------------------- matvec + list push per point
// One warp per point. Lane l computes channels [4l,4l+3] via shuffle-broadcast
// matvec, stores them contiguously (coalesced 512B/warp, NO atomics on data).
__global__ void compute_kernel(const int* __restrict__ coords,
                               const float* __restrict__ feats,
                               const float* __restrict__ kernel,
                               const int* __restrict__ stride_p,
                               int n_points)
{
    int p    = (blockIdx.x * blockDim.x + threadIdx.x) >> 5;
    int lane = threadIdx.x & 31;
    if (p >= n_points) return;

    int s  = stride_p[0];
    int4 c4 = ((const int4*)coords)[p];
    int cell = c4.w * (BEV_H * BEV_W) + (c4.x / s) * BEV_W + (c4.z / s);
    int kidx = c4.y / s;

    const float* fp = feats + (size_t)p * C_IN;
    float f0 = fp[lane];
    float f1 = fp[lane + 32];

    const float4* kp = (const float4*)(kernel + (size_t)kidx * C_IN * C_OUT);

    float4 acc = make_float4(0.f, 0.f, 0.f, 0.f);
#pragma unroll
    for (int k = 0; k < C_IN; k++) {
        float fk = __shfl_sync(0xFFFFFFFFu, (k < 32) ? f0 : f1, k & 31);
        float4 w = kp[k * (C_OUT / 4) + lane];
        acc.x = fmaf(fk, w.x, acc.x);
        acc.y = fmaf(fk, w.y, acc.y);
        acc.z = fmaf(fk, w.z, acc.z);
        acc.w = fmaf(fk, w.w, acc.w);
    }

    ((float4*)g_pointbuf)[(size_t)p * (C_OUT / 4) + lane] = acc;

    if (lane == 0) {
        int old = atomicExch(&g_head[cell], p + 1);   // lock-free list push
        g_next[p] = old;
    }
}

// ------------------------------------------------------- expand / transpose out
// One block per (b,x) row. Coalesced gather of occupied cells (sum chains) into
// smem, stream output with __stcs float4 stores, reset consumed head entries.
__global__ void expand_kernel(float* __restrict__ out)
{
    __shared__ float staged[CAP * PITCH];          // 41.3 KB
    __shared__ short slot_of_z[BEV_W];
    __shared__ int   pt_of_slot[BEV_W];
    __shared__ int   nslots;

    int row = blockIdx.x;                          // b * BEV_H + x
    int b   = row >> 9;
    int x   = row & (BEV_H - 1);
    int tid = threadIdx.x;

    if (tid == 0) nslots = 0;
    __syncthreads();

    // Phase A: scan head[], compact occupied z's, reset head (invariant).
#pragma unroll
    for (int z = tid; z < BEV_W; z += 256) {
        int h = g_head[row * BEV_W + z];
        if (h) {
            int sl = atomicAdd(&nslots, 1);
            slot_of_z[z] = (short)sl;
            pt_of_slot[sl] = h;
            g_head[row * BEV_W + z] = 0;
        } else {
            slot_of_z[z] = -1;
        }
    }
    __syncthreads();

    int ns = nslots;
    int nstage = ns < CAP ? ns : CAP;

    // Phase B: coalesced 512B-per-point gathers (sum rare multi-point chains).
    for (int i = tid; i < nstage * C_OUT; i += 256) {
        int sl = i >> 7, c = i & 127;
        int p = pt_of_slot[sl];
        float v = 0.f;
        while (p) {
            v += g_pointbuf[(size_t)(p - 1) * C_OUT + c];
            p = g_next[p - 1];
        }
        staged[sl * PITCH + c] = v;
    }
    __syncthreads();

    // Phase C: stream output. thread -> (z-float4 q, channel parity cp).
    int q  = tid & 127;
    int cp = tid >> 7;
    int z0 = q * 4;
    int s0 = slot_of_z[z0 + 0];
    int s1 = slot_of_z[z0 + 1];
    int s2 = slot_of_z[z0 + 2];
    int s3 = slot_of_z[z0 + 3];

#pragma unroll 4
    for (int cb = 0; cb < C_OUT; cb += 2) {
        int c = cb + cp;
        float4 v;
        float* sv[4] = {&v.x, &v.y, &v.z, &v.w};
        int ss[4] = {s0, s1, s2, s3};
#pragma unroll
        for (int j = 0; j < 4; j++) {
            int sl = ss[j];
            float r = 0.f;
            if (sl >= 0) {
                if (sl < CAP) {
                    r = staged[sl * PITCH + c];
                } else {                     // overflow fallback (never in practice)
                    int p = pt_of_slot[sl];
                    while (p) {
                        r += g_pointbuf[(size_t)(p - 1) * C_OUT + c];
                        p = g_next[p - 1];
                    }
                }
            }
            *sv[j] = r;
        }
        size_t o = (((size_t)(b * C_OUT + c) * BEV_H + x) * BEV_W) >> 2;
        __stcs(((float4*)out) + o + q, v);
    }
}

extern "C" void kernel_launch(void* const* d_in, const int* in_sizes, int n_in,
                              void* d_out, int out_size)
{
    const int*   coords = (const int*)d_in[0];
    const float* feats  = (const float*)d_in[1];
    const float* kern   = (const float*)d_in[2];
    const int*   stride = (const int*)d_in[3];

    int n_points = in_sizes[1] / C_IN;

    // 1. matvec + compact store + per-cell list push
    int wpb = 8;
    int blocks = (n_points + wpb - 1) / wpb;
    compute_kernel<<<blocks, wpb * 32>>>(coords, feats, kern, stride, n_points);

    // 2. stream final output + reset head[] (self-maintaining invariant)
    expand_kernel<<<BATCH * BEV_H, 256>>>((float*)d_out);
}

// round 9
// speedup vs baseline: 1.3854x; 1.1867x over previous
#include <cuda_runtime.h>
#include <cuda_bf16.h>

#define C_IN   64
#define C_OUT  128
#define BEV_H  512
#define BEV_W  512
#define BATCH  2
#define NKER   16

#define N_CELLS  (BATCH * BEV_H * BEV_W)     // 524288
#define MAX_PTS  (1 << 17)                   // 131072 (N=40000)
#define BINCAP   8192                        // max points per kidx bin
#define BPB      128                         // blocks per bin (BINCAP/64)
#define CAP      80                          // staged cells per row
#define PITCH    129                         // odd pitch -> conflict-free

// Invariant: g_head is ALL-ZERO at every kernel_launch entry (zero at module
// load; expand_kernel resets every entry it consumed). 0 = empty, else p+1.
__device__ int   g_head[N_CELLS];                       // 2 MB
__device__ int   g_next[MAX_PTS];
__device__ float g_pointbuf[(size_t)MAX_PTS * C_OUT];   // compact results
__device__ int   g_bincnt[NKER];
__device__ int   g_binlist[NKER * BINCAP];

// ---------------------------------------------------------------- bin counters
__global__ void clear_bins_kernel()
{
    if (threadIdx.x < NKER) g_bincnt[threadIdx.x] = 0;
}

// ------------------------------------- bucket-append points by kidx (16 bins)
__global__ void bin_kernel(const int* __restrict__ coords,
                           const int* __restrict__ stride_p, int n)
{
    int i    = blockIdx.x * blockDim.x + threadIdx.x;
    int lane = threadIdx.x & 31;
    bool act = i < n;
    int kidx = act ? (coords[i * 4 + 1] / stride_p[0]) : NKER;

    unsigned mask  = __match_any_sync(0xFFFFFFFFu, kidx);
    int leader     = __ffs(mask) - 1;
    int cnt        = __popc(mask);
    int rank       = __popc(mask & ((1u << lane) - 1u));
    int base = 0;
    if (lane == leader && kidx < NKER)
        base = atomicAdd(&g_bincnt[kidx], cnt);
    base = __shfl_sync(0xFFFFFFFFu, base, leader);
    if (act) g_binlist[kidx * BINCAP + base + rank] = i;
}

// --------------------------------------------------------------- tiled matvec
// Block loads ONE 32KB weight matrix to smem; each of 8 warps processes 8
// same-bin points (features in regs, shuffle-broadcast, 8x float4 acc).
__global__ void __launch_bounds__(256)
compute_kernel(const int* __restrict__ coords,
               const float* __restrict__ feats,
               const float* __restrict__ kernel,
               const int* __restrict__ stride_p)
{
    __shared__ float4 ks4[C_IN * C_OUT / 4];            // 32 KB

    int bin   = blockIdx.x >> 7;                        // / BPB
    int chunk = blockIdx.x & (BPB - 1);
    int cnt   = g_bincnt[bin];
    int start = chunk * 64;
    if (start >= cnt) return;                           // uniform

    const float4* kg = (const float4*)(kernel + (size_t)bin * C_IN * C_OUT);
    for (int i = threadIdx.x; i < C_IN * C_OUT / 4; i += 256) ks4[i] = kg[i];
    __syncthreads();

    int w    = threadIdx.x >> 5;
    int lane = threadIdx.x & 31;
    int pbase = start + w * 8;
    if (pbase >= cnt) return;                           // warp-uniform
    int npts = min(8, cnt - pbase);

    int   pidx[8];
    float f0[8], f1[8];
#pragma unroll
    for (int r = 0; r < 8; r++) {
        int idx = pbase + (r < npts ? r : 0);
        int p   = g_binlist[bin * BINCAP + idx];
        pidx[r] = p;
        f0[r] = feats[(size_t)p * C_IN + lane];
        f1[r] = feats[(size_t)p * C_IN + 32 + lane];
    }

    float4 acc[8];
#pragma unroll
    for (int r = 0; r < 8; r++) acc[r] = make_float4(0.f, 0.f, 0.f, 0.f);

#pragma unroll
    for (int k = 0; k < C_IN; k++) {
        float4 w4 = ks4[k * 32 + lane];
#pragma unroll
        for (int r = 0; r < 8; r++) {
            float fk = __shfl_sync(0xFFFFFFFFu, (k < 32) ? f0[r] : f1[r], k & 31);
            acc[r].x = fmaf(fk, w4.x, acc[r].x);
            acc[r].y = fmaf(fk, w4.y, acc[r].y);
            acc[r].z = fmaf(fk, w4.z, acc[r].z);
            acc[r].w = fmaf(fk, w4.w, acc[r].w);
        }
    }

#pragma unroll
    for (int r = 0; r < 8; r++) {
        if (r >= npts) break;
        ((float4*)g_pointbuf)[(size_t)pidx[r] * (C_OUT / 4) + lane] = acc[r];
    }

    if (lane == 0) {
        int s = stride_p[0];
        for (int r = 0; r < npts; r++) {
            int p = pidx[r];
            int4 c4 = ((const int4*)coords)[p];
            int cell = c4.w * (BEV_H * BEV_W) + (c4.x / s) * BEV_W + (c4.z / s);
            int old = atomicExch(&g_head[cell], p + 1);
            g_next[p] = old;
        }
    }
}

// ------------------------------------------------------- expand / transpose out
// One block per (b,x) row. Compact occupied z's, gather into smem (chain-sum),
// then BRANCHLESS store stream: empty/overflow slots map to a zeroed smem row.
__global__ void expand_kernel(float* __restrict__ out)
{
    __shared__ float staged[(CAP + 1) * PITCH];    // row CAP = zeros
    __shared__ short slot_of_z[BEV_W];
    __shared__ short z_of_slot[BEV_W];
    __shared__ int   pt_of_slot[BEV_W];
    __shared__ int   nslots;

    int row = blockIdx.x;                          // b * BEV_H + x
    int b   = row >> 9;
    int x   = row & (BEV_H - 1);
    int tid = threadIdx.x;

    if (tid == 0) nslots = 0;
    if (tid < PITCH) staged[CAP * PITCH + tid] = 0.f;
    __syncthreads();

    // Phase A: compact occupied z's; reset head[] (restores invariant).
#pragma unroll
    for (int z = tid; z < BEV_W; z += 256) {
        int h = g_head[row * BEV_W + z];
        if (h) {
            int sl = atomicAdd(&nslots, 1);
            slot_of_z[z]   = (short)sl;
            z_of_slot[sl]  = (short)z;
            pt_of_slot[sl] = h;
            g_head[row * BEV_W + z] = 0;
        } else {
            slot_of_z[z] = -1;
        }
    }
    __syncthreads();

    int ns = nslots;
    int nstage = ns < CAP ? ns : CAP;

    // Phase B: coalesced 512B-per-cell gathers (sum rare multi-point chains).
    for (int i = tid; i < nstage * C_OUT; i += 256) {
        int sl = i >> 7, c = i & 127;
        int p = pt_of_slot[sl];
        float v = 0.f;
        while (p) {
            v += g_pointbuf[(size_t)(p - 1) * C_OUT + c];
            p = g_next[p - 1];
        }
        staged[sl * PITCH + c] = v;
    }
    __syncthreads();

    // Phase C: branchless output stream. thread -> (z-quad q, channel parity cp).
    int q  = tid & 127;
    int cp = tid >> 7;
    int z0 = q * 4;
    unsigned s0 = (unsigned)(int)slot_of_z[z0 + 0]; if (s0 >= CAP) s0 = CAP;
    unsigned s1 = (unsigned)(int)slot_of_z[z0 + 1]; if (s1 >= CAP) s1 = CAP;
    unsigned s2 = (unsigned)(int)slot_of_z[z0 + 2]; if (s2 >= CAP) s2 = CAP;
    unsigned s3 = (unsigned)(int)slot_of_z[z0 + 3]; if (s3 >= CAP) s3 = CAP;

    const float* b0 = staged + s0 * PITCH + cp;
    const float* b1 = staged + s1 * PITCH + cp;
    const float* b2 = staged + s2 * PITCH + cp;
    const float* b3 = staged + s3 * PITCH + cp;

    float4* op = (float4*)out
               + ((size_t)(b * C_OUT + cp) * BEV_H + x) * (BEV_W / 4) + q;

#pragma unroll
    for (int cb = 0; cb < C_OUT; cb += 2) {
        float4 v = make_float4(b0[cb], b1[cb], b2[cb], b3[cb]);
        __stcs(op, v);
        op += (size_t)2 * BEV_H * BEV_W / 4;
    }

    // Overflow fixup (ns > CAP never occurs in practice; kept for correctness).
    if (ns > CAP) {
        __syncthreads();
        for (int i = tid; i < (ns - CAP) * C_OUT; i += 256) {
            int sl = CAP + (i >> 7), c = i & 127;
            int p = pt_of_slot[sl];
            float v = 0.f;
            while (p) {
                v += g_pointbuf[(size_t)(p - 1) * C_OUT + c];
                p = g_next[p - 1];
            }
            out[((size_t)(b * C_OUT + c) * BEV_H + x) * BEV_W + z_of_slot[sl]] = v;
        }
    }
}

extern "C" void kernel_launch(void* const* d_in, const int* in_sizes, int n_in,
                              void* d_out, int out_size)
{
    const int*   coords = (const int*)d_in[0];
    const float* feats  = (const float*)d_in[1];
    const float* kern   = (const float*)d_in[2];
    const int*   stride = (const int*)d_in[3];

    int n_points = in_sizes[1] / C_IN;

    // 1. bucket points by kidx (cheap, warp-aggregated)
    clear_bins_kernel<<<1, 32>>>();
    bin_kernel<<<(n_points + 255) / 256, 256>>>(coords, stride, n_points);

    // 2. smem-tiled matvec (one weight matrix per block) + list push
    compute_kernel<<<NKER * BPB, 256>>>(coords, feats, kern, stride);

    // 3. stream final output + reset head[] (self-maintaining invariant)
    expand_kernel<<<BATCH * BEV_H, 256>>>((float*)d_out);
}

// round 13
// speedup vs baseline: 1.4995x; 1.0824x over previous
#include <cuda_runtime.h>
#include <cuda_bf16.h>

#define C_IN   64
#define C_OUT  128
#define BEV_H  512
#define BEV_W  512
#define BATCH  2
#define NKER   16

#define N_CELLS  (BATCH * BEV_H * BEV_W)     // 524288
#define MAX_PTS  (1 << 17)                   // 131072 (N=40000)
#define BINCAP   8192                        // max points per kidx bin
#define BPB      128                         // blocks per bin (BINCAP/64)
#define CAP      80                          // staged cells per row
#define CHALF    64                          // channels per expand block
#define HPITCH   65                          // odd pitch -> conflict-free

// g_head cleared at the start of every launch by clear_head_kernel.
__device__ int   g_head[N_CELLS];                       // 2 MB
__device__ int   g_next[MAX_PTS];
__device__ float g_pointbuf[(size_t)MAX_PTS * C_OUT];   // compact results
__device__ int   g_bincnt[NKER];
__device__ int   g_binlist[NKER * BINCAP];

// ----------------------------------------------------------------- clears
__global__ void clear_head_kernel()
{
    int i = blockIdx.x * blockDim.x + threadIdx.x;      // int4 index
    ((int4*)g_head)[i] = make_int4(0, 0, 0, 0);
}

__global__ void clear_bins_kernel()
{
    if (threadIdx.x < NKER) g_bincnt[threadIdx.x] = 0;
}

// ------------------------------------- bucket-append points by kidx (16 bins)
__global__ void bin_kernel(const int* __restrict__ coords,
                           const int* __restrict__ stride_p, int n)
{
    int i    = blockIdx.x * blockDim.x + threadIdx.x;
    int lane = threadIdx.x & 31;
    bool act = i < n;
    int kidx = act ? (coords[i * 4 + 1] / stride_p[0]) : NKER;

    unsigned mask  = __match_any_sync(0xFFFFFFFFu, kidx);
    int leader     = __ffs(mask) - 1;
    int cnt        = __popc(mask);
    int rank       = __popc(mask & ((1u << lane) - 1u));
    int base = 0;
    if (lane == leader && kidx < NKER)
        base = atomicAdd(&g_bincnt[kidx], cnt);
    base = __shfl_sync(0xFFFFFFFFu, base, leader);
    if (act) g_binlist[kidx * BINCAP + base + rank] = i;
}

// --------------------------------------------------------------- tiled matvec
// Block loads ONE 32KB weight matrix to smem; each of 8 warps processes 8
// same-bin points (features in regs, shuffle-broadcast, 8x float4 acc).
__global__ void __launch_bounds__(256)
compute_kernel(const int* __restrict__ coords,
               const float* __restrict__ feats,
               const float* __restrict__ kernel,
               const int* __restrict__ stride_p)
{
    __shared__ float4 ks4[C_IN * C_OUT / 4];            // 32 KB

    int bin   = blockIdx.x >> 7;                        // / BPB
    int chunk = blockIdx.x & (BPB - 1);
    int cnt   = g_bincnt[bin];
    int start = chunk * 64;
    if (start >= cnt) return;                           // uniform

    const float4* kg = (const float4*)(kernel + (size_t)bin * C_IN * C_OUT);
    for (int i = threadIdx.x; i < C_IN * C_OUT / 4; i += 256) ks4[i] = kg[i];
    __syncthreads();

    int w    = threadIdx.x >> 5;
    int lane = threadIdx.x & 31;
    int pbase = start + w * 8;
    if (pbase >= cnt) return;                           // warp-uniform
    int npts = min(8, cnt - pbase);

    int   pidx[8];
    float f0[8], f1[8];
#pragma unroll
    for (int r = 0; r < 8; r++) {
        int idx = pbase + (r < npts ? r : 0);
        int p   = g_binlist[bin * BINCAP + idx];
        pidx[r] = p;
        f0[r] = feats[(size_t)p * C_IN + lane];
        f1[r] = feats[(size_t)p * C_IN + 32 + lane];
    }

    float4 acc[8];
#pragma unroll
    for (int r = 0; r < 8; r++) acc[r] = make_float4(0.f, 0.f, 0.f, 0.f);

#pragma unroll
    for (int k = 0; k < C_IN; k++) {
        float4 w4 = ks4[k * 32 + lane];
#pragma unroll
        for (int r = 0; r < 8; r++) {
            float fk = __shfl_sync(0xFFFFFFFFu, (k < 32) ? f0[r] : f1[r], k & 31);
            acc[r].x = fmaf(fk, w4.x, acc[r].x);
            acc[r].y = fmaf(fk, w4.y, acc[r].y);
            acc[r].z = fmaf(fk, w4.z, acc[r].z);
            acc[r].w = fmaf(fk, w4.w, acc[r].w);
        }
    }

#pragma unroll
    for (int r = 0; r < 8; r++) {
        if (r >= npts) break;
        ((float4*)g_pointbuf)[(size_t)pidx[r] * (C_OUT / 4) + lane] = acc[r];
    }

    if (lane == 0) {
        int s = stride_p[0];
        for (int r = 0; r < npts; r++) {
            int p = pidx[r];
            int4 c4 = ((const int4*)coords)[p];
            int cell = c4.w * (BEV_H * BEV_W) + (c4.x / s) * BEV_W + (c4.z / s);
            int old = atomicExch(&g_head[cell], p + 1);
            g_next[p] = old;
        }
    }
}

// ------------------------------------------------------- expand / transpose out
// TWO blocks per (b,x) row, each owning 64 channels -> ~24KB smem -> 8
// blocks/SM (full occupancy). head[] is read-only here (cleared separately).
__global__ void __launch_bounds__(256) expand_kernel(float* __restrict__ out)
{
    __shared__ float staged[(CAP + 1) * HPITCH];   // ~21 KB, row CAP = zeros
    __shared__ short slot_of_z[BEV_W];
    __shared__ short z_of_slot[BEV_W];
    __shared__ int   pt_of_slot[BEV_W];
    __shared__ int   nslots;

    int row    = blockIdx.x >> 1;                  // b * BEV_H + x
    int chbase = (blockIdx.x & 1) * CHALF;         // channel half
    int b      = row >> 9;
    int x      = row & (BEV_H - 1);
    int tid    = threadIdx.x;

    if (tid == 0) nslots = 0;
    if (tid < HPITCH) staged[CAP * HPITCH + tid] = 0.f;
    __syncthreads();

    // Phase A: compact occupied z's (read-only scan of head[]).
#pragma unroll
    for (int z = tid; z < BEV_W; z += 256) {
        int h = g_head[row * BEV_W + z];
        if (h) {
            int sl = atomicAdd(&nslots, 1);
            slot_of_z[z]   = (short)sl;
            z_of_slot[sl]  = (short)z;
            pt_of_slot[sl] = h;
        } else {
            slot_of_z[z] = -1;
        }
    }
    __syncthreads();

    int ns = nslots;
    int nstage = ns < CAP ? ns : CAP;

    // Phase B: gather this block's 64-channel half of each occupied cell
    // (coalesced 256B per cell; disjoint between the two half-blocks).
    for (int i = tid; i < nstage * CHALF; i += 256) {
        int sl = i >> 6, c = i & (CHALF - 1);
        int p = pt_of_slot[sl];
        float v = 0.f;
        while (p) {
            v += g_pointbuf[(size_t)(p - 1) * C_OUT + chbase + c];
            p = g_next[p - 1];
        }
        staged[sl * HPITCH + c] = v;
    }
    __syncthreads();

    // Phase C: branchless store stream. thread -> (z-quad q, channel parity cp).
    int q  = tid & 127;
    int cp = tid >> 7;
    int z0 = q * 4;
    unsigned s0 = (unsigned)(int)slot_of_z[z0 + 0]; if (s0 >= CAP) s0 = CAP;
    unsigned s1 = (unsigned)(int)slot_of_z[z0 + 1]; if (s1 >= CAP) s1 = CAP;
    unsigned s2 = (unsigned)(int)slot_of_z[z0 + 2]; if (s2 >= CAP) s2 = CAP;
    unsigned s3 = (unsigned)(int)slot_of_z[z0 + 3]; if (s3 >= CAP) s3 = CAP;

    const float* b0 = staged + s0 * HPITCH + cp;
    const float* b1 = staged + s1 * HPITCH + cp;
    const float* b2 = staged + s2 * HPITCH + cp;
    const float* b3 = staged + s3 * HPITCH + cp;

    float4* op = (float4*)out
               + ((size_t)(b * C_OUT + chbase + cp) * BEV_H + x) * (BEV_W / 4) + q;

#pragma unroll
    for (int cb = 0; cb < CHALF; cb += 2) {
        float4 v = make_float4(b0[cb], b1[cb], b2[cb], b3[cb]);
        __stcs(op, v);
        op += (size_t)2 * BEV_H * BEV_W / 4;
    }

    // Overflow fixup (ns > CAP never occurs in practice; kept for correctness).
    if (ns > CAP) {
        __syncthreads();
        for (int i = tid; i < (ns - CAP) * CHALF; i += 256) {
            int sl = CAP + (i >> 6), c = i & (CHALF - 1);
            int p = pt_of_slot[sl];
            float v = 0.f;
            while (p) {
                v += g_pointbuf[(size_t)(p - 1) * C_OUT + chbase + c];
                p = g_next[p - 1];
            }
            out[((size_t)(b * C_OUT + chbase + c) * BEV_H + x) * BEV_W
                + z_of_slot[sl]] = v;
        }
    }
}

extern "C" void kernel_launch(void* const* d_in, const int* in_sizes, int n_in,
                              void* d_out, int out_size)
{
    const int*   coords = (const int*)d_in[0];
    const float* feats  = (const float*)d_in[1];
    const float* kern   = (const float*)d_in[2];
    const int*   stride = (const int*)d_in[3];

    int n_points = in_sizes[1] / C_IN;

    // 1. clear per-launch state (head list + bin counters)
    clear_head_kernel<<<N_CELLS / 4 / 256, 256>>>();
    clear_bins_kernel<<<1, 32>>>();

    // 2. bucket points by kidx (warp-aggregated)
    bin_kernel<<<(n_points + 255) / 256, 256>>>(coords, stride, n_points);

    // 3. smem-tiled matvec (one weight matrix per block) + list push
    compute_kernel<<<NKER * BPB, 256>>>(coords, feats, kern, stride);

    // 4. stream final output (2 channel-half blocks per row, full occupancy)
    expand_kernel<<<BATCH * BEV_H * 2, 256>>>((float*)d_out);
}

// round 17
// speedup vs baseline: 1.6634x; 1.1093x over previous
#include <cuda_runtime.h>
#include <cuda_bf16.h>

#define C_IN   64
#define C_OUT  128
#define BEV_H  512
#define BEV_W  512
#define BATCH  2
#define NKER   16

#define N_CELLS  (BATCH * BEV_H * BEV_W)     // 524288
#define MAX_PTS  (1 << 17)                   // 131072 (N=40000)
#define BINCAP   8192                        // max points per kidx bin
#define TILE_PTS 64                          // points per compute block
#define BPB      (BINCAP / TILE_PTS)         // 128 blocks per bin
#define CAP      80                          // staged cells per expand row
#define CHALF    64                          // channels per expand block
#define HPITCH   65                          // odd pitch -> conflict-free

// g_head cleared at the start of every launch by clear_head_kernel.
__device__ int   g_head[N_CELLS];                       // 2 MB
__device__ int   g_next[MAX_PTS];
__device__ float g_pointbuf[(size_t)MAX_PTS * C_OUT];   // compact results
__device__ int   g_bincnt[NKER];
__device__ int   g_binlist[NKER * BINCAP];

// packed dual-FMA: acc(2xf32) += f(2xf32) * w(2xf32)   [Blackwell f32x2 pipe]
#define FMA2(acc, f, w) \
    asm("fma.rn.f32x2 %0, %1, %2, %0;" : "+l"(acc) : "l"(f), "l"(w))

// ----------------------------------------------------------------- clears
__global__ void clear_head_kernel()
{
    int i = blockIdx.x * blockDim.x + threadIdx.x;      // int4 index
    ((int4*)g_head)[i] = make_int4(0, 0, 0, 0);
}

__global__ void clear_bins_kernel()
{
    if (threadIdx.x < NKER) g_bincnt[threadIdx.x] = 0;
}

// ------------------------------------- bucket-append points by kidx (16 bins)
__global__ void bin_kernel(const int* __restrict__ coords,
                           const int* __restrict__ stride_p, int n)
{
    int i    = blockIdx.x * blockDim.x + threadIdx.x;
    int lane = threadIdx.x & 31;
    bool act = i < n;
    int kidx = act ? (coords[i * 4 + 1] / stride_p[0]) : NKER;

    unsigned mask  = __match_any_sync(0xFFFFFFFFu, kidx);
    int leader     = __ffs(mask) - 1;
    int cnt        = __popc(mask);
    int rank       = __popc(mask & ((1u << lane) - 1u));
    int base = 0;
    if (lane == leader && kidx < NKER)
        base = atomicAdd(&g_bincnt[kidx], cnt);
    base = __shfl_sync(0xFFFFFFFFu, base, leader);
    if (act) g_binlist[kidx * BINCAP + base + rank] = i;
}

// ------------------------------------------------- tiled matvec, f32x2 packed
// Block: 64 points x 128 channels of ONE bin. Thread = 8 pts x 4 ch.
// Features staged in smem pre-duplicated as (f,f) pairs -> LDS.128 yields two
// ready f32x2 broadcast operands; weights float4 = two f32x2 operands.
// Inner loop per thread per k: 5x LDS.128 + 16x fma.f32x2 (no shuffles).
__global__ void __launch_bounds__(256)
compute_kernel(const int* __restrict__ coords,
               const float* __restrict__ feats,
               const float* __restrict__ kernel,
               const int* __restrict__ stride_p)
{
    extern __shared__ char cs[];
    float*  ws     = (float*)cs;                        // [64][128]  32 KB
    float2* fs2    = (float2*)(cs + 32768);             // [64][64]   32 KB (dup)
    int*    pidx_s = (int*)(cs + 65536);                // [64]

    int bin   = blockIdx.x >> 7;                        // / BPB
    int chunk = blockIdx.x & (BPB - 1);
    int cnt   = g_bincnt[bin];
    int start = chunk * TILE_PTS;
    if (start >= cnt) return;                           // uniform exit
    int n_blk = min(TILE_PTS, cnt - start);

    int tid = threadIdx.x;

    // point index list (clamped duplicates for tail; their stores are masked)
    if (tid < TILE_PTS)
        pidx_s[tid] = g_binlist[bin * BINCAP + min(start + tid, cnt - 1)];

    // stage weights: 32KB coalesced float4 copy
    {
        const float4* kg = (const float4*)(kernel + (size_t)bin * C_IN * C_OUT);
        float4* wd = (float4*)ws;
#pragma unroll
        for (int i = tid; i < C_IN * C_OUT / 4; i += 256) wd[i] = kg[i];
    }
    __syncthreads();

    // parallel head-push: 64 independent atomics (was: serial lane-0 chains)
    if (tid < n_blk) {
        int p = pidx_s[tid];
        int s = stride_p[0];
        int4 c4 = ((const int4*)coords)[p];
        int cell = c4.w * (BEV_H * BEV_W) + (c4.x / s) * BEV_W + (c4.z / s);
        int old = atomicExch(&g_head[cell], p + 1);
        g_next[p] = old;
    }

    // stage features transposed+duplicated: fs2[k][pt] = (f,f).
    // thread: pt = tid&63 (lane-consecutive -> conflict-free STS.64),
    //         kq = tid>>6 owns 16 k's. Global reads are sector-dense.
    {
        int pt = tid & 63;
        int kq = tid >> 6;
        const float4* fg = (const float4*)(feats + (size_t)pidx_s[pt] * C_IN
                                           + kq * 16);
#pragma unroll
        for (int j = 0; j < 4; j++) {
            float4 v = fg[j];
            int kb = kq * 16 + j * 4;
            fs2[(kb + 0) * 64 + pt] = make_float2(v.x, v.x);
            fs2[(kb + 1) * 64 + pt] = make_float2(v.y, v.y);
            fs2[(kb + 2) * 64 + pt] = make_float2(v.z, v.z);
            fs2[(kb + 3) * 64 + pt] = make_float2(v.w, v.w);
        }
    }
    __syncthreads();

    int pg = tid >> 5;                                  // point group (8 pts)
    int cg = tid & 31;                                  // channel group (4 ch)

    unsigned long long a[8][2];
#pragma unroll
    for (int r = 0; r < 8; r++) { a[r][0] = 0ull; a[r][1] = 0ull; }

#pragma unroll 8
    for (int k = 0; k < C_IN; k++) {
        const ulonglong2* fp = (const ulonglong2*)(fs2 + (k << 6) + (pg << 3));
        ulonglong2 f01 = fp[0];                         // pts 0,1 (dup pairs)
        ulonglong2 f23 = fp[1];
        ulonglong2 f45 = fp[2];
        ulonglong2 f67 = fp[3];
        ulonglong2 wv  = *(const ulonglong2*)(ws + (k << 7) + (cg << 2));

        FMA2(a[0][0], f01.x, wv.x); FMA2(a[0][1], f01.x, wv.y);
        FMA2(a[1][0], f01.y, wv.x); FMA2(a[1][1], f01.y, wv.y);
        FMA2(a[2][0], f23.x, wv.x); FMA2(a[2][1], f23.x, wv.y);
        FMA2(a[3][0], f23.y, wv.x); FMA2(a[3][1], f23.y, wv.y);
        FMA2(a[4][0], f45.x, wv.x); FMA2(a[4][1], f45.x, wv.y);
        FMA2(a[5][0], f45.y, wv.x); FMA2(a[5][1], f45.y, wv.y);
        FMA2(a[6][0], f67.x, wv.x); FMA2(a[6][1], f67.x, wv.y);
        FMA2(a[7][0], f67.y, wv.x); FMA2(a[7][1], f67.y, wv.y);
    }

    // store: per point, warp writes 512B contiguous (lane = 4 channels)
#pragma unroll
    for (int r = 0; r < 8; r++) {
        int pt = pg * 8 + r;
        if (pt < n_blk) {
            float2 lo = *(float2*)&a[r][0];
            float2 hi = *(float2*)&a[r][1];
            ((float4*)g_pointbuf)[(size_t)pidx_s[pt] * (C_OUT / 4) + cg] =
                make_float4(lo.x, lo.y, hi.x, hi.y);
        }
    }
}

// ------------------------------------------------------- expand / transpose out
// TWO blocks per (b,x) row, each owning 64 channels -> ~24KB smem -> 8
// blocks/SM (full occupancy). head[] is read-only here (cleared separately).
__global__ void __launch_bounds__(256) expand_kernel(float* __restrict__ out)
{
    __shared__ float staged[(CAP + 1) * HPITCH];   // ~21 KB, row CAP = zeros
    __shared__ short slot_of_z[BEV_W];
    __shared__ short z_of_slot[BEV_W];
    __shared__ int   pt_of_slot[BEV_W];
    __shared__ int   nslots;

    int row    = blockIdx.x >> 1;                  // b * BEV_H + x
    int chbase = (blockIdx.x & 1) * CHALF;         // channel half
    int b      = row >> 9;
    int x      = row & (BEV_H - 1);
    int tid    = threadIdx.x;

    if (tid == 0) nslots = 0;
    if (tid < HPITCH) staged[CAP * HPITCH + tid] = 0.f;
    __syncthreads();

    // Phase A: compact occupied z's (read-only scan of head[]).
#pragma unroll
    for (int z = tid; z < BEV_W; z += 256) {
        int h = g_head[row * BEV_W + z];
        if (h) {
            int sl = atomicAdd(&nslots, 1);
            slot_of_z[z]   = (short)sl;
            z_of_slot[sl]  = (short)z;
            pt_of_slot[sl] = h;
        } else {
            slot_of_z[z] = -1;
        }
    }
    __syncthreads();

    int ns = nslots;
    int nstage = ns < CAP ? ns : CAP;

    // Phase B: gather this block's 64-channel half of each occupied cell
    // (coalesced 256B per cell; disjoint between the two half-blocks).
    for (int i = tid; i < nstage * CHALF; i += 256) {
        int sl = i >> 6, c = i & (CHALF - 1);
        int p = pt_of_slot[sl];
        float v = 0.f;
        while (p) {
            v += g_pointbuf[(size_t)(p - 1) * C_OUT + chbase + c];
            p = g_next[p - 1];
        }
        staged[sl * HPITCH + c] = v;
    }
    __syncthreads();

    // Phase C: branchless store stream. thread -> (z-quad q, channel parity cp).
    int q  = tid & 127;
    int cp = tid >> 7;
    int z0 = q * 4;
    unsigned s0 = (unsigned)(int)slot_of_z[z0 + 0]; if (s0 >= CAP) s0 = CAP;
    unsigned s1 = (unsigned)(int)slot_of_z[z0 + 1]; if (s1 >= CAP) s1 = CAP;
    unsigned s2 = (unsigned)(int)slot_of_z[z0 + 2]; if (s2 >= CAP) s2 = CAP;
    unsigned s3 = (unsigned)(int)slot_of_z[z0 + 3]; if (s3 >= CAP) s3 = CAP;

    const float* b0 = staged + s0 * HPITCH + cp;
    const float* b1 = staged + s1 * HPITCH + cp;
    const float* b2 = staged + s2 * HPITCH + cp;
    const float* b3 = staged + s3 * HPITCH + cp;

    float4* op = (float4*)out
               + ((size_t)(b * C_OUT + chbase + cp) * BEV_H + x) * (BEV_W / 4) + q;

#pragma unroll
    for (int cb = 0; cb < CHALF; cb += 2) {
        float4 v = make_float4(b0[cb], b1[cb], b2[cb], b3[cb]);
        __stcs(op, v);
        op += (size_t)2 * BEV_H * BEV_W / 4;
    }

    // Overflow fixup (ns > CAP never occurs in practice; kept for correctness).
    if (ns > CAP) {
        __syncthreads();
        for (int i = tid; i < (ns - CAP) * CHALF; i += 256) {
            int sl = CAP + (i >> 6), c = i & (CHALF - 1);
            int p = pt_of_slot[sl];
            float v = 0.f;
            while (p) {
                v += g_pointbuf[(size_t)(p - 1) * C_OUT + chbase + c];
                p = g_next[p - 1];
            }
            out[((size_t)(b * C_OUT + chbase + c) * BEV_H + x) * BEV_W
                + z_of_slot[sl]] = v;
        }
    }
}

extern "C" void kernel_launch(void* const* d_in, const int* in_sizes, int n_in,
                              void* d_out, int out_size)
{
    const int*   coords = (const int*)d_in[0];
    const float* feats  = (const float*)d_in[1];
    const float* kern   = (const float*)d_in[2];
    const int*   stride = (const int*)d_in[3];

    int n_points = in_sizes[1] / C_IN;

    static int smem_set = 0;
    if (!smem_set) {
        cudaFuncSetAttribute(compute_kernel,
                             cudaFuncAttributeMaxDynamicSharedMemorySize,
                             66 * 1024);
        smem_set = 1;
    }

    // 1. clear per-launch state (head list + bin counters)
    clear_head_kernel<<<N_CELLS / 4 / 256, 256>>>();
    clear_bins_kernel<<<1, 32>>>();

    // 2. bucket points by kidx (warp-aggregated)
    bin_kernel<<<(n_points + 255) / 256, 256>>>(coords, stride, n_points);

    // 3. smem-tiled f32x2 matvec (one weight matrix per block) + head push
    compute_kernel<<<NKER * BPB, 256, 66 * 1024>>>(coords, feats, kern, stride);

    // 4. stream final output (2 channel-half blocks per row, full occupancy)
    expand_kernel<<<BATCH * BEV_H * 2, 256>>>((float*)d_out);
}